// round 17
// baseline (speedup 1.0000x reference)
#include <cuda_runtime.h>
#include <cuda_bf16.h>
#include <mma.h>

using namespace nvcuda;

#define ULL unsigned long long

__device__ __forceinline__ ULL pack2(float a, float b) {
    ULL r; asm("mov.b64 %0, {%1, %2};" : "=l"(r) : "f"(a), "f"(b)); return r;
}
__device__ __forceinline__ void unpack2(ULL v, float& a, float& b) {
    asm("mov.b64 {%0, %1}, %2;" : "=f"(a), "=f"(b) : "l"(v));
}
__device__ __forceinline__ ULL fma2(ULL a, ULL b, ULL c) {
    ULL d; asm("fma.rn.f32x2 %0, %1, %2, %3;" : "=l"(d) : "l"(a), "l"(b), "l"(c)); return d;
}
__device__ __forceinline__ void cpa16(unsigned dst, const void* src, bool v) {
    int sz = v ? 16 : 0;
    asm volatile("cp.async.cg.shared.global [%0], [%1], 16, %2;" :: "r"(dst), "l"(src), "r"(sz));
}
__device__ __forceinline__ void cp_commit() { asm volatile("cp.async.commit_group;"); }
template <int N> __device__ __forceinline__ void cp_wait() {
    asm volatile("cp.async.wait_group %0;" :: "n"(N));
}

__device__ float g_bufA[8 * 128 * 256 * 256];
__device__ float g_bufB[8 * 128 * 256 * 256];
__device__ float g_bufC[8 * 128 * 256 * 256];
__device__ float g_cbT[128 * 1024];
__device__ float g_cnorm[1024];
__device__ double g_loss;
__device__ __nv_bfloat16 g_clX[8ll * 65536 * 128];
__device__ __nv_bfloat16 g_clY[8ll * 65536 * 128];
__device__ __nv_bfloat16 g_wA[162 * 8192];

// weight prep: per (tap,chunk) tile [co(128 pad)][ci_l(64)] bf16, hi plane then lo.
__global__ void wprep_k(const float* __restrict__ w, int COUT, int CIN, int base)
{
    const int NC = CIN >> 6;
    int e = blockIdx.x * 256 + threadIdx.x;
    if (e >= 9 * NC * 8192) return;
    int ci_l = e & 63, co = (e >> 6) & 127, rest = e >> 13;
    int c = rest % NC, k = rest / NC;
    float val = (co < COUT) ? w[(co * CIN + c * 64 + ci_l) * 9 + k] : 0.f;
    __nv_bfloat16 hi = __float2bfloat16(val);
    __nv_bfloat16 lo = __float2bfloat16(val - __bfloat162float(hi));
    __nv_bfloat16* tile = g_wA + (long)(base + k * NC + c) * 16384 + co * 64 + ci_l;
    tile[0] = hi;
    tile[8192] = lo;
}

// NCHW fp32 -> channel-last hi/lo bf16 (smem transpose, coalesced both sides)
template <int C>
__global__ void __launch_bounds__(256) clprep_k(
    const float* __restrict__ in, __nv_bfloat16* __restrict__ cl, int H, int W)
{
    __shared__ float sm[C * 65];
    const int t = threadIdx.x, x0 = blockIdx.x * 64, y = blockIdx.y, b = blockIdx.z;
    for (int e = t; e < C * 64; e += 256) {
        int ci = e >> 6, px = e & 63;
        sm[ci * 65 + px] = in[((b * C + ci) * H + y) * W + x0 + px];
    }
    __syncthreads();
    int px = t >> 2, q = t & 3;
    if (q * 32 < C) {
        long pix = ((long)b * H + y) * W + x0 + px;
        __nv_bfloat16* dh = cl + pix * 2 * C + q * 32;
#pragma unroll
        for (int j = 0; j < 32; j++) {
            float v = sm[(q * 32 + j) * 65 + px];
            __nv_bfloat16 h = __float2bfloat16(v);
            dh[j] = h;
            dh[C + j] = __float2bfloat16(v - __bfloat162float(h));
        }
    }
}

// ---------------------------------------------------------------------------
// wmma decoder conv: D[co(128)][px(128)] = sum_{taps,chunks} W x I, hi/lo 3-pass.
// Block 256 thr = 8 warps (4M x 2N); warp tile M32 x N64 (2x4 wmma frags).
// smem buffer (per stage): A_hi[128x72] A_lo B_hi B_lo bf16 (73728 B), x2 buf.
// ---------------------------------------------------------------------------
template <int CIN, bool UPS, bool SKIP, bool RELU>
__global__ void __launch_bounds__(256, 1) tconv_k(
    const __nv_bfloat16* __restrict__ cl, const __nv_bfloat16* __restrict__ wt,
    const float* __restrict__ bias, const float* __restrict__ skip_in,
    float* __restrict__ out, int OH, int OW, int COUT)
{
    constexpr int NC = CIN >> 6;
    constexpr int NT = 9 * NC;
    constexpr unsigned BUFB = 73728;          // bytes per stage buffer
    extern __shared__ __align__(16) char smem[];
    __nv_bfloat16* smb = (__nv_bfloat16*)smem;
    const unsigned sbase = (unsigned)__cvta_generic_to_shared(smem);

    const int t = threadIdx.x, wid = t >> 5;
    const int m0 = (wid & 3) * 32, n0 = (wid >> 2) * 64;
    const int b = blockIdx.z, y = blockIdx.y, x0 = blockIdx.x * 128;
    const int IW = UPS ? (OW >> 1) : OW;
    const int IHp = UPS ? (OH >> 1) : OH;

    auto stage = [&](int i, int buf) {
        const int k = i / NC, c = i - k * NC;
        const int dy = k / 3 - 1, dx = k % 3 - 1;
        const int gy = y + dy;
        const bool vy = (unsigned)gy < (unsigned)OH;
        const int iy = UPS ? (gy >> 1) : gy;
        const __nv_bfloat16* wtile = wt + (long)i * 16384;
        unsigned dbase = sbase + buf * BUFB;
#pragma unroll
        for (int j = 0; j < 16; j++) {
            int e = t + 256 * j;                 // 4096 chunks of 16B
            int ch = e & 7, row = (e >> 3) & 127, plane = (e >> 10) & 1, isB = e >> 11;
            unsigned dst = dbase + (unsigned)(isB * 36864 + plane * 18432 + row * 144 + ch * 16);
            if (!isB) {
                cpa16(dst, wtile + plane * 8192 + row * 64 + ch * 8, true);
            } else {
                int gx = x0 + row + dx;
                bool v = vy && (unsigned)gx < (unsigned)OW;
                int ix = UPS ? (gx >> 1) : gx;
                long pix = v ? (((long)b * IHp + iy) * IW + ix) : 0;
                const __nv_bfloat16* sp = cl +
                    (pix * (2 * CIN) + plane * CIN + c * 64 + ch * 8);
                cpa16(dst, sp, v);
            }
        }
        cp_commit();
    };

    wmma::fragment<wmma::accumulator, 16, 16, 16, float> acc[2][4];
#pragma unroll
    for (int i = 0; i < 2; i++)
#pragma unroll
        for (int j = 0; j < 4; j++) wmma::fill_fragment(acc[i][j], 0.f);

    stage(0, 0);
#pragma unroll 1
    for (int i = 0; i < NT; i++) {
        cp_wait<0>();
        __syncthreads();
        if (i + 1 < NT) stage(i + 1, (i + 1) & 1);
        const __nv_bfloat16* sbuf = smb + (i & 1) * (BUFB / 2);   // elems
#pragma unroll 1
        for (int p = 0; p < 3; p++) {
            const __nv_bfloat16* Ap = sbuf + (p == 2 ? 9216 : 0);
            const __nv_bfloat16* Bp = sbuf + 18432 + (p == 1 ? 9216 : 0);
#pragma unroll
            for (int kc = 0; kc < 4; kc++) {
                wmma::fragment<wmma::matrix_a, 16, 16, 16, __nv_bfloat16, wmma::row_major> af[2];
                wmma::fragment<wmma::matrix_b, 16, 16, 16, __nv_bfloat16, wmma::col_major> bf[4];
#pragma unroll
                for (int ii = 0; ii < 2; ii++)
                    wmma::load_matrix_sync(af[ii], Ap + (m0 + 16 * ii) * 72 + kc * 16, 72);
#pragma unroll
                for (int jj = 0; jj < 4; jj++)
                    wmma::load_matrix_sync(bf[jj], Bp + (n0 + 16 * jj) * 72 + kc * 16, 72);
#pragma unroll
                for (int ii = 0; ii < 2; ii++)
#pragma unroll
                    for (int jj = 0; jj < 4; jj++)
                        wmma::mma_sync(acc[ii][jj], af[ii], bf[jj], acc[ii][jj]);
            }
        }
    }
    __syncthreads();

    // D -> smem (fp32, ld 136), then coalesced NCHW epilogue
    float* D = (float*)smem;
#pragma unroll
    for (int ii = 0; ii < 2; ii++)
#pragma unroll
        for (int jj = 0; jj < 4; jj++)
            wmma::store_matrix_sync(D + (m0 + 16 * ii) * 136 + n0 + 16 * jj,
                                    acc[ii][jj], 136, wmma::mem_row_major);
    __syncthreads();

    const int px = t & 127;
#pragma unroll 1
    for (int co = t >> 7; co < COUT; co += 2) {
        float o = D[co * 136 + px] + bias[co];
        const long gidx = (((long)b * COUT + co) * OH + y) * OW + x0 + px;
        if (SKIP) o += skip_in[gidx];
        if (RELU) o = fmaxf(o, 0.f);
        out[gidx] = o;
    }
}

// ---------------------------------------------------------------------------
// Encoder stride-1 conv (unchanged R12 path, bit-exact).
// ---------------------------------------------------------------------------
template <int CIN, int CIB, bool RELU, int SKIP>
__global__ void __launch_bounds__(256, 2) conv3x3n_k(
    const float* __restrict__ in, const float* __restrict__ wgt,
    const float* __restrict__ bias,
    const float* __restrict__ skip_in, const float* __restrict__ skip_w,
    const float* __restrict__ skip_b,
    float* __restrict__ out,
    int IH, int IW, int OH, int OW, int COUT, int CSKIP, int nG)
{
    constexpr int WCI = (CIN > 64) ? 64 : CIN;
    extern __shared__ __align__(16) char smem_raw[];
    float* tiles = (float*)smem_raw;
    ULL* wall = (ULL*)(smem_raw + 2 * CIB * 2448 * sizeof(float));

    const int t = threadIdx.x;
    const int tx = t & 15, ty = t >> 4;
    const int b = blockIdx.z / nG;
    const int co0 = (blockIdx.z - b * nG) * 8;
    const int ox0 = blockIdx.x * 64 + 4 * tx;
    const int oy0 = blockIdx.y * 32 + 2 * ty;
    const int x0a = blockIdx.x * 64 - 4;
    const int y0 = blockIdx.y * 32 - 1;

    const unsigned tiles_s = (unsigned)__cvta_generic_to_shared(tiles);

    auto stage = [&](int ci0, int buf) {
        unsigned tb = tiles_s + buf * (CIB * 2448 * 4);
        constexpr int NCH = CIB * 612;
#pragma unroll
        for (int j = 0; j < (NCH + 255) / 256; j++) {
            int e = t + 256 * j;
            if (e < NCH) {
                int ci_l = e / 612, rem = e - ci_l * 612;
                int row = rem / 18, c16 = rem - row * 18;
                int gy = y0 + row, gx = x0a + 4 * c16;
                bool v = (unsigned)gy < (unsigned)IH && (unsigned)gx < (unsigned)IW;
                const float* inc = in + (b * CIN + ci0 + ci_l) * (IH * IW);
                const float* sp = inc + (v ? (gy * IW + gx) : 0);
                cpa16(tb + (ci_l * 2448 + row * 72 + 4 * c16) * 4, sp, v);
            }
        }
        cp_commit();
    };
    auto load_wall = [&](int cbase) {
        for (int e = t; e < WCI * 36; e += 256) {
            int ci_l = e / 36, r = e - ci_l * 36;
            int k = r >> 2, p = r & 3;
            int ca = co0 + 2 * p, ci = cbase + ci_l;
            float wa = (ca < COUT) ? wgt[(ca * CIN + ci) * 9 + k] : 0.f;
            float wb = (ca + 1 < COUT) ? wgt[((ca + 1) * CIN + ci) * 9 + k] : 0.f;
            wall[e] = pack2(wa, wb);
        }
    };

    ULL acc[2][4][4];
#pragma unroll
    for (int py = 0; py < 2; py++)
#pragma unroll
        for (int px = 0; px < 4; px++)
#pragma unroll
            for (int p = 0; p < 4; p++) acc[py][px][p] = 0ull;

    constexpr int NR = CIN / CIB;
    stage(0, 0);
    load_wall(0);

#pragma unroll 1
    for (int i = 0; i < NR; i++) {
        cp_wait<0>();
        __syncthreads();
        if (CIN > WCI && i * CIB == WCI) { load_wall(WCI); __syncthreads(); }
        if (i + 1 < NR) stage((i + 1) * CIB, (i + 1) & 1);
        const float* tbuf = tiles + (i & 1) * (CIB * 2448);
#pragma unroll
        for (int ci_l = 0; ci_l < CIB; ci_l++) {
            const float* tci = tbuf + ci_l * 2448;
            float rv[4][6];
#pragma unroll
            for (int r = 0; r < 4; r++) {
                const float* p = &tci[(2 * ty + r) * 72 + 4 * tx];
                float4 a = *(const float4*)p;
                float4 b4 = *(const float4*)(p + 4);
                rv[r][0] = a.w;
                rv[r][1] = b4.x; rv[r][2] = b4.y; rv[r][3] = b4.z; rv[r][4] = b4.w;
                rv[r][5] = p[8];
            }
            const ulonglong2* wsc = (const ulonglong2*)(wall +
                ((CIN > 64) ? ((i * CIB + ci_l) & 63) : (i * CIB + ci_l)) * 36);
#pragma unroll
            for (int ky = 0; ky < 3; ky++) {
#pragma unroll
                for (int kx = 0; kx < 3; kx++) {
                    const int k = ky * 3 + kx;
                    ulonglong2 wA = wsc[k * 2];
                    ulonglong2 wB = wsc[k * 2 + 1];
#pragma unroll
                    for (int py = 0; py < 2; py++) {
#pragma unroll
                        for (int px = 0; px < 4; px++) {
                            float v = rv[py + ky][px + kx];
                            ULL vv = pack2(v, v);
                            acc[py][px][0] = fma2(vv, wA.x, acc[py][px][0]);
                            acc[py][px][1] = fma2(vv, wA.y, acc[py][px][1]);
                            acc[py][px][2] = fma2(vv, wB.x, acc[py][px][2]);
                            acc[py][px][3] = fma2(vv, wB.y, acc[py][px][3]);
                        }
                    }
                }
            }
        }
    }

    if (SKIP == 2) {
        __syncthreads();
        float4* tiles4 = (float4*)tiles;
#pragma unroll 1
        for (int cs0 = 0; cs0 < CSKIP; cs0 += 8) {
#pragma unroll
            for (int cs_l = 0; cs_l < 8; cs_l++) {
                const float4* sp4 = (const float4*)(skip_in
                    + ((b * CSKIP + cs0 + cs_l) * OH + blockIdx.y * 32) * OW + blockIdx.x * 64);
#pragma unroll
                for (int j = 0; j < 2; j++) {
                    int f = t + 256 * j;
                    int row = f >> 4, c4 = f & 15;
                    tiles4[cs_l * 512 + f] = sp4[row * (OW >> 2) + c4];
                }
            }
            if (t < 32) {
                int cs_l = t >> 2, p = t & 3;
                int ca = co0 + 2 * p;
                float wa = (ca < COUT) ? skip_w[ca * CSKIP + cs0 + cs_l] : 0.f;
                float wb = (ca + 1 < COUT) ? skip_w[(ca + 1) * CSKIP + cs0 + cs_l] : 0.f;
                wall[t] = pack2(wa, wb);
            }
            __syncthreads();
#pragma unroll
            for (int cs_l = 0; cs_l < 8; cs_l++) {
                ulonglong2 wA = ((const ulonglong2*)wall)[cs_l * 2];
                ulonglong2 wB = ((const ulonglong2*)wall)[cs_l * 2 + 1];
#pragma unroll
                for (int py = 0; py < 2; py++) {
                    float4 s4 = *(const float4*)&tiles[cs_l * 2048 + (2 * ty + py) * 64 + 4 * tx];
                    float sv[4] = {s4.x, s4.y, s4.z, s4.w};
#pragma unroll
                    for (int px = 0; px < 4; px++) {
                        ULL vv = pack2(sv[px], sv[px]);
                        acc[py][px][0] = fma2(vv, wA.x, acc[py][px][0]);
                        acc[py][px][1] = fma2(vv, wA.y, acc[py][px][1]);
                        acc[py][px][2] = fma2(vv, wB.x, acc[py][px][2]);
                        acc[py][px][3] = fma2(vv, wB.y, acc[py][px][3]);
                    }
                }
            }
            __syncthreads();
        }
    }

    float bv[8];
#pragma unroll
    for (int c = 0; c < 8; c++) bv[c] = (co0 + c < COUT) ? bias[co0 + c] : 0.f;
#pragma unroll
    for (int c = 0; c < 8; c++) {
        const int co = co0 + c;
        if (co < COUT) {
            const int p = c >> 1, hi = c & 1;
#pragma unroll
            for (int py = 0; py < 2; py++) {
                float o[4];
#pragma unroll
                for (int px = 0; px < 4; px++) {
                    float a0, a1;
                    unpack2(acc[py][px][p], a0, a1);
                    o[px] = (hi ? a1 : a0) + bv[c];
                }
                const int base = ((b * COUT + co) * OH + oy0 + py) * OW + ox0;
                if (SKIP == 1) {
                    float4 s = *(const float4*)&skip_in[base];
                    o[0] += s.x; o[1] += s.y; o[2] += s.z; o[3] += s.w;
                }
                if (SKIP == 2) {
                    float sb2 = skip_b[co];
#pragma unroll
                    for (int px = 0; px < 4; px++) o[px] += sb2;
                }
                if (RELU) {
#pragma unroll
                    for (int px = 0; px < 4; px++) o[px] = fmaxf(o[px], 0.f);
                }
                float4 ov; ov.x = o[0]; ov.y = o[1]; ov.z = o[2]; ov.w = o[3];
                *(float4*)&out[base] = ov;
            }
        }
    }
}

// ---------------------------------------------------------------------------
// Stride-2 conv (unchanged R12).
// ---------------------------------------------------------------------------
template <int CIN, int CIB>
__global__ void __launch_bounds__(256, 2) conv3x3s2_k(
    const float* __restrict__ in, const float* __restrict__ wgt,
    const float* __restrict__ bias, float* __restrict__ out,
    int IH, int IW, int OH, int OW, int COUT, int nG)
{
    constexpr int WCI = (CIN > 64) ? 64 : CIN;
    extern __shared__ __align__(16) char smem_raw[];
    float* tiles = (float*)smem_raw;
    ULL* wall = (ULL*)(smem_raw + 2 * CIB * 4680 * sizeof(float));

    const int t = threadIdx.x;
    const int tx = t & 15, ty = t >> 4;
    const int b = blockIdx.z / nG;
    const int co0 = (blockIdx.z - b * nG) * 8;
    const int ox0 = blockIdx.x * 32, oy0 = blockIdx.y * 32;
    const int x0a = blockIdx.x * 64 - 4, y0 = blockIdx.y * 64 - 1;
    const unsigned tiles_s = (unsigned)__cvta_generic_to_shared(tiles);

    auto stage = [&](int ci0, int buf) {
        unsigned tb = tiles_s + buf * (CIB * 4680 * 4);
        constexpr int NCH = CIB * 1170;
#pragma unroll
        for (int j = 0; j < (NCH + 255) / 256; j++) {
            int e = t + 256 * j;
            if (e < NCH) {
                int ci_l = e / 1170, rem = e - ci_l * 1170;
                int row = rem / 18, c16 = rem - row * 18;
                int gy = y0 + row, gx = x0a + 4 * c16;
                bool v = (unsigned)gy < (unsigned)IH && (unsigned)gx < (unsigned)IW;
                const float* inc = in + (b * CIN + ci0 + ci_l) * (IH * IW);
                const float* sp = inc + (v ? (gy * IW + gx) : 0);
                cpa16(tb + (ci_l * 4680 + row * 72 + 4 * c16) * 4, sp, v);
            }
        }
        cp_commit();
    };
    auto load_wall = [&](int cbase) {
        for (int e = t; e < WCI * 36; e += 256) {
            int ci_l = e / 36, r = e - ci_l * 36;
            int k = r >> 2, p = r & 3;
            int ca = co0 + 2 * p, ci = cbase + ci_l;
            float wa = (ca < COUT) ? wgt[(ca * CIN + ci) * 9 + k] : 0.f;
            float wb = (ca + 1 < COUT) ? wgt[((ca + 1) * CIN + ci) * 9 + k] : 0.f;
            wall[e] = pack2(wa, wb);
        }
    };

    ULL acc[2][2][4];
#pragma unroll
    for (int py = 0; py < 2; py++)
#pragma unroll
        for (int px = 0; px < 2; px++)
#pragma unroll
            for (int p = 0; p < 4; p++) acc[py][px][p] = 0ull;

    constexpr int NR = CIN / CIB;
    stage(0, 0);
    load_wall(0);

#pragma unroll 1
    for (int i = 0; i < NR; i++) {
        cp_wait<0>();
        __syncthreads();
        if (CIN > WCI && i * CIB == WCI) { load_wall(WCI); __syncthreads(); }
        if (i + 1 < NR) stage((i + 1) * CIB, (i + 1) & 1);
        const float* tbuf = tiles + (i & 1) * (CIB * 4680);
#pragma unroll
        for (int ci_l = 0; ci_l < CIB; ci_l++) {
            const float* tci = tbuf + ci_l * 4680;
            float rv[5][5];
#pragma unroll
            for (int r = 0; r < 5; r++) {
                const float* p = &tci[(4 * ty + r) * 72 + 4 * tx];
                float4 a = *(const float4*)p;
                float4 b4 = *(const float4*)(p + 4);
                rv[r][0] = a.w;
                rv[r][1] = b4.x; rv[r][2] = b4.y; rv[r][3] = b4.z; rv[r][4] = b4.w;
            }
            const ulonglong2* wsc = (const ulonglong2*)(wall +
                ((CIN > 64) ? ((i * CIB + ci_l) & 63) : (i * CIB + ci_l)) * 36);
#pragma unroll
            for (int ky = 0; ky < 3; ky++) {
#pragma unroll
                for (int kx = 0; kx < 3; kx++) {
                    const int k = ky * 3 + kx;
                    ulonglong2 wA = wsc[k * 2];
                    ulonglong2 wB = wsc[k * 2 + 1];
#pragma unroll
                    for (int py = 0; py < 2; py++) {
#pragma unroll
                        for (int px = 0; px < 2; px++) {
                            float v = rv[2 * py + ky][2 * px + kx];
                            ULL vv = pack2(v, v);
                            acc[py][px][0] = fma2(vv, wA.x, acc[py][px][0]);
                            acc[py][px][1] = fma2(vv, wA.y, acc[py][px][1]);
                            acc[py][px][2] = fma2(vv, wB.x, acc[py][px][2]);
                            acc[py][px][3] = fma2(vv, wB.y, acc[py][px][3]);
                        }
                    }
                }
            }
        }
    }
#pragma unroll
    for (int c = 0; c < 8; c++) {
        const int co = co0 + c;
        if (co < COUT) {
            const float bb = bias[co];
            const int p = c >> 1, hi = c & 1;
#pragma unroll
            for (int py = 0; py < 2; py++) {
                float o[2];
#pragma unroll
                for (int px = 0; px < 2; px++) {
                    float a0, a1;
                    unpack2(acc[py][px][p], a0, a1);
                    o[px] = fmaxf((hi ? a1 : a0) + bb, 0.f);
                }
                float2 ov; ov.x = o[0]; ov.y = o[1];
                *(float2*)&out[((b * COUT + co) * OH + oy0 + 2 * ty + py) * OW + ox0 + 2 * tx] = ov;
            }
        }
    }
}

__device__ __forceinline__ float warp_sumsq_128(const float* __restrict__ x, int lane)
{
    float s = 0.f;
#pragma unroll
    for (int i = 0; i < 4; i++) {
        float v = x[lane + 32 * i];
        s = __fadd_rn(s, __fmul_rn(v, v));
    }
#pragma unroll
    for (int off = 16; off > 0; off >>= 1)
        s = __fadd_rn(s, __shfl_down_sync(0xffffffffu, s, off));
    return s;
}

__global__ void __launch_bounds__(256) prep_cnorm_k(const float* __restrict__ cb)
{
    if (blockIdx.x == 0 && threadIdx.x == 0) g_loss = 0.0;
    int warp = (blockIdx.x * 256 + threadIdx.x) >> 5;
    int lane = threadIdx.x & 31;
    if (warp < 1024) {
        float s = warp_sumsq_128(cb + warp * 128, lane);
        if (lane == 0) g_cnorm[warp] = s;
    }
}

__global__ void __launch_bounds__(256) transpose_cb_k(const float* __restrict__ cb)
{
    int i = blockIdx.x * 256 + threadIdx.x;
    int code = i >> 7, k = i & 127;
    g_cbT[k * 1024 + code] = cb[i];
}

__global__ void __launch_bounds__(256) quantize_k(
    const float* __restrict__ z, const float* __restrict__ cb, float* __restrict__ qst)
{
    __shared__ float ct[8 * 1024];
    __shared__ float zs[16 * 128];
    __shared__ float znorm_s[16];
    __shared__ float cand_d[16][8];
    __shared__ int   cand_i[16][8];
    __shared__ int   kbest_s[16];
    __shared__ double red[256];

    const int t = threadIdx.x;
    const int lane = t & 31, w = t >> 5;
    const long long row0 = (long long)blockIdx.x * 16;
    {
        const float4* zg = (const float4*)(z + row0 * 128);
        float4* z4 = (float4*)zs;
#pragma unroll
        for (int j = 0; j < 2; j++) z4[t + 256 * j] = zg[t + 256 * j];
    }
    __syncthreads();
#pragma unroll
    for (int rr = 0; rr < 2; rr++) {
        int r = w + 8 * rr;
        float s = warp_sumsq_128(zs + r * 128, lane);
        if (lane == 0) znorm_s[r] = s;
    }
    ULL acc[16][2];
#pragma unroll
    for (int r = 0; r < 16; r++) { acc[r][0] = 0ull; acc[r][1] = 0ull; }
#pragma unroll 1
    for (int kt = 0; kt < 16; kt++) {
        __syncthreads();
        {
            const float4* gt = (const float4*)(g_cbT + kt * 8 * 1024);
            float4* c4s = (float4*)ct;
#pragma unroll
            for (int j = 0; j < 8; j++) c4s[t + 256 * j] = gt[t + 256 * j];
        }
        __syncthreads();
#pragma unroll
        for (int kk = 0; kk < 8; kk++) {
            float4 c4 = ((const float4*)ct)[kk * 256 + t];
            ULL cab = pack2(c4.x, c4.y);
            ULL ccd = pack2(c4.z, c4.w);
            const int k = kt * 8 + kk;
#pragma unroll
            for (int r = 0; r < 16; r++) {
                float zk = zs[r * 128 + k];
                ULL zz = pack2(zk, zk);
                acc[r][0] = fma2(zz, cab, acc[r][0]);
                acc[r][1] = fma2(zz, ccd, acc[r][1]);
            }
        }
    }
    __syncthreads();
    float4 cn4 = *(const float4*)(g_cnorm + 4 * t);
#pragma unroll
    for (int r = 0; r < 16; r++) {
        float a, b, c, d;
        unpack2(acc[r][0], a, b);
        unpack2(acc[r][1], c, d);
        float zn = znorm_s[r];
        float d0 = __fadd_rn(__fsub_rn(zn, __fmul_rn(2.f, a)), cn4.x);
        float d1 = __fadd_rn(__fsub_rn(zn, __fmul_rn(2.f, b)), cn4.y);
        float d2 = __fadd_rn(__fsub_rn(zn, __fmul_rn(2.f, c)), cn4.z);
        float d3 = __fadd_rn(__fsub_rn(zn, __fmul_rn(2.f, d)), cn4.w);
        float bv = d0; int bi = 4 * t;
        if (d1 < bv) { bv = d1; bi = 4 * t + 1; }
        if (d2 < bv) { bv = d2; bi = 4 * t + 2; }
        if (d3 < bv) { bv = d3; bi = 4 * t + 3; }
#pragma unroll
        for (int off = 16; off > 0; off >>= 1) {
            float ov = __shfl_down_sync(0xffffffffu, bv, off);
            int   oi = __shfl_down_sync(0xffffffffu, bi, off);
            if (ov < bv || (ov == bv && oi < bi)) { bv = ov; bi = oi; }
        }
        if (lane == 0) { cand_d[r][w] = bv; cand_i[r][w] = bi; }
    }
    __syncthreads();
    if (t < 16) {
        float bv = cand_d[t][0]; int bi = cand_i[t][0];
#pragma unroll
        for (int j = 1; j < 8; j++) {
            float ov = cand_d[t][j]; int oi = cand_i[t][j];
            if (ov < bv || (ov == bv && oi < bi)) { bv = ov; bi = oi; }
        }
        kbest_s[t] = bi;
    }
    __syncthreads();
    double ls = 0.0;
#pragma unroll
    for (int j = 0; j < 8; j++) {
        int e = j * 256 + t;
        int r = e >> 7, col = e & 127;
        float zv = zs[r * 128 + col];
        float qv = cb[kbest_s[r] * 128 + col];
        float qz = __fsub_rn(qv, zv);
        float st = __fadd_rn(zv, qz);
        qst[(row0 + r) * 128 + col] = st;
        ls += (double)qz * (double)qz;
    }
    red[t] = ls;
    __syncthreads();
    for (int s = 128; s > 0; s >>= 1) {
        if (t < s) red[t] += red[t + s];
        __syncthreads();
    }
    if (t == 0) atomicAdd(&g_loss, red[0]);
}

__global__ void finish_k(float* __restrict__ out, int start, int total)
{
    float v = (float)(1.25 * g_loss / 16777216.0);
    for (int i = start + threadIdx.x; i < total; i += 32) out[i] = v;
}

// ---------------------------------------------------------------------------
extern "C" void kernel_launch(void* const* d_in, const int* in_sizes, int n_in,
                              void* d_out, int out_size)
{
    const float* x        = (const float*)d_in[0];
    const float* enc_in_w = (const float*)d_in[1];
    const float* enc_in_b = (const float*)d_in[2];
    const float* rb0_w1   = (const float*)d_in[3];
    const float* rb0_b1   = (const float*)d_in[4];
    const float* rb0_w2   = (const float*)d_in[5];
    const float* rb0_b2   = (const float*)d_in[6];
    const float* rb1_w1   = (const float*)d_in[7];
    const float* rb1_b1   = (const float*)d_in[8];
    const float* rb1_w2   = (const float*)d_in[9];
    const float* rb1_b2   = (const float*)d_in[10];
    const float* rb1_ws   = (const float*)d_in[11];
    const float* rb1_bs   = (const float*)d_in[12];
    const float* down_w   = (const float*)d_in[13];
    const float* down_b   = (const float*)d_in[14];
    const float* codebook = (const float*)d_in[15];
    const float* d1_w1    = (const float*)d_in[16];
    const float* d1_b1    = (const float*)d_in[17];
    const float* d1_w2    = (const float*)d_in[18];
    const float* d1_b2    = (const float*)d_in[19];
    const float* up_w     = (const float*)d_in[20];
    const float* up_b     = (const float*)d_in[21];
    const float* d0_w1    = (const float*)d_in[22];
    const float* d0_b1    = (const float*)d_in[23];
    const float* d0_w2    = (const float*)d_in[24];
    const float* d0_b2    = (const float*)d_in[25];
    const float* out_w    = (const float*)d_in[26];
    const float* out_b    = (const float*)d_in[27];
    float* out = (float*)d_out;

    float *bufA, *bufB, *bufC;
    cudaGetSymbolAddress((void**)&bufA, g_bufA);
    cudaGetSymbolAddress((void**)&bufB, g_bufB);
    cudaGetSymbolAddress((void**)&bufC, g_bufC);
    __nv_bfloat16 *clX, *clY, *wA;
    cudaGetSymbolAddress((void**)&clX, g_clX);
    cudaGetSymbolAddress((void**)&clY, g_clY);
    cudaGetSymbolAddress((void**)&wA, g_wA);

    const int SM_3   = 2 * 3 * 2448 * 4 + 3 * 36 * 8;
    const int SM_64  = 2 * 4 * 2448 * 4 + 64 * 36 * 8;
    const int SM_S2  = 2 * 2 * 4680 * 4 + 64 * 36 * 8;
    const int SM_TC  = 2 * 73728;                        // 147456

    cudaFuncSetAttribute(conv3x3n_k<3, 3, false, 0>,  cudaFuncAttributeMaxDynamicSharedMemorySize, SM_3);
    cudaFuncSetAttribute(conv3x3n_k<64, 4, true, 0>,  cudaFuncAttributeMaxDynamicSharedMemorySize, SM_64);
    cudaFuncSetAttribute(conv3x3n_k<64, 4, true, 1>,  cudaFuncAttributeMaxDynamicSharedMemorySize, SM_64);
    cudaFuncSetAttribute(conv3x3n_k<128, 4, true, 2>, cudaFuncAttributeMaxDynamicSharedMemorySize, SM_64);
    cudaFuncSetAttribute(conv3x3s2_k<128, 2>,         cudaFuncAttributeMaxDynamicSharedMemorySize, SM_S2);
    cudaFuncSetAttribute(tconv_k<128, false, false, true>, cudaFuncAttributeMaxDynamicSharedMemorySize, SM_TC);
    cudaFuncSetAttribute(tconv_k<128, false, true,  true>, cudaFuncAttributeMaxDynamicSharedMemorySize, SM_TC);
    cudaFuncSetAttribute(tconv_k<128, true,  false, true>, cudaFuncAttributeMaxDynamicSharedMemorySize, SM_TC);
    cudaFuncSetAttribute(tconv_k<64, false, false, true>,  cudaFuncAttributeMaxDynamicSharedMemorySize, SM_TC);
    cudaFuncSetAttribute(tconv_k<64, false, true,  true>,  cudaFuncAttributeMaxDynamicSharedMemorySize, SM_TC);
    cudaFuncSetAttribute(tconv_k<64, false, false, false>, cudaFuncAttributeMaxDynamicSharedMemorySize, SM_TC);

    const int B = 8;
    dim3 G256_64(4, 8, B * 8);
    dim3 G256_128(4, 8, B * 16);
    dim3 GS2(4, 4, B * 16);

    transpose_cb_k<<<512, 256>>>(codebook);
    prep_cnorm_k<<<128, 256>>>(codebook);

    // decoder weight prep (independent)
    wprep_k<<<576, 256>>>(d1_w1, 128, 128, 0);
    wprep_k<<<576, 256>>>(d1_w2, 128, 128, 18);
    wprep_k<<<576, 256>>>(up_w, 64, 128, 36);
    wprep_k<<<288, 256>>>(d0_w1, 64, 64, 54);
    wprep_k<<<288, 256>>>(d0_w2, 64, 64, 63);
    wprep_k<<<288, 256>>>(out_w, 3, 64, 72);

    // ---- encoder (bit-exact FFMA2 path) ----
    conv3x3n_k<3, 3, false, 0><<<G256_64, 256, SM_3>>>(
        x, enc_in_w, enc_in_b, nullptr, nullptr, nullptr, bufA, 256, 256, 256, 256, 64, 0, 8);
    conv3x3n_k<64, 4, true, 0><<<G256_64, 256, SM_64>>>(
        bufA, rb0_w1, rb0_b1, nullptr, nullptr, nullptr, bufB, 256, 256, 256, 256, 64, 0, 8);
    conv3x3n_k<64, 4, true, 1><<<G256_64, 256, SM_64>>>(
        bufB, rb0_w2, rb0_b2, bufA, nullptr, nullptr, bufC, 256, 256, 256, 256, 64, 0, 8);
    conv3x3n_k<64, 4, true, 0><<<G256_128, 256, SM_64>>>(
        bufC, rb1_w1, rb1_b1, nullptr, nullptr, nullptr, bufA, 256, 256, 256, 256, 128, 0, 16);
    conv3x3n_k<128, 4, true, 2><<<G256_128, 256, SM_64>>>(
        bufA, rb1_w2, rb1_b2, bufC, rb1_ws, rb1_bs, bufB, 256, 256, 256, 256, 128, 64, 16);
    conv3x3s2_k<128, 2><<<GS2, 256, SM_S2>>>(
        bufB, down_w, down_b, bufC, 256, 256, 128, 128, 128, 16);

    // ---- quantizer (bit-exact) ----
    quantize_k<<<8192, 256>>>(bufC, codebook, bufA);   // qst -> bufA

    // ---- decoder on wmma/HMMA tensor cores ----
    clprep_k<128><<<dim3(2, 128, 8), 256>>>(bufA, clX, 128, 128);
    tconv_k<128, false, false, true><<<dim3(1, 128, 8), 256, SM_TC>>>(
        clX, wA, d1_b1, nullptr, bufB, 128, 128, 128);
    clprep_k<128><<<dim3(2, 128, 8), 256>>>(bufB, clY, 128, 128);
    tconv_k<128, false, true, true><<<dim3(1, 128, 8), 256, SM_TC>>>(
        clY, wA + 18ll * 16384, d1_b2, bufA, bufC, 128, 128, 128);
    clprep_k<128><<<dim3(2, 128, 8), 256>>>(bufC, clX, 128, 128);
    tconv_k<128, true, false, true><<<dim3(2, 256, 8), 256, SM_TC>>>(
        clX, wA + 36ll * 16384, up_b, nullptr, bufA, 256, 256, 64);
    clprep_k<64><<<dim3(4, 256, 8), 256>>>(bufA, clY, 256, 256);
    tconv_k<64, false, false, true><<<dim3(2, 256, 8), 256, SM_TC>>>(
        clY, wA + 54ll * 16384, d0_b1, nullptr, bufB, 256, 256, 64);
    clprep_k<64><<<dim3(4, 256, 8), 256>>>(bufB, clX, 256, 256);
    tconv_k<64, false, true, true><<<dim3(2, 256, 8), 256, SM_TC>>>(
        clX, wA + 63ll * 16384, d0_b2, bufA, bufC, 256, 256, 64);
    clprep_k<64><<<dim3(4, 256, 8), 256>>>(bufC, clY, 256, 256);
    tconv_k<64, false, false, false><<<dim3(2, 256, 8), 256, SM_TC>>>(
        clY, wA + 72ll * 16384, out_b, nullptr, out, 256, 256, 3);

    const int recon = 8 * 3 * 256 * 256;
    if (out_size > recon) finish_k<<<1, 32>>>(out, recon, out_size);
}